// round 6
// baseline (speedup 1.0000x reference)
#include <cuda_runtime.h>
#include <cuda_bf16.h>
#include <cstdint>
#include <cstring>

// Problem constants
#define BB 4
#define SS 8192
#define FF 1024
#define HH 16
#define DD 64
#define MM (BB * SS)          // 32768 rows for projections
#define NROWS (BB * HH * SS)  // 524288 LN rows
#define ATT_ELEMS ((size_t)BB * SS * FF)       // 33554432
#define P_ELEMS   ((size_t)BB * HH * DD * DD)  // 262144

// Scratch (device globals: allocation-free rule)
__device__ float g_q[ATT_ELEMS];
__device__ float g_k[ATT_ELEMS];
__device__ float g_v[ATT_ELEMS];
__device__ __nv_bfloat16 g_wth[3 * FF * FF];  // W^T hi, per weight
__device__ __nv_bfloat16 g_wtl[3 * FF * FF];  // W^T lo, per weight

// ---------------------------------------------------------------------------
// mma.sync helpers (arch-portable: ldmatrix sm_75+, bf16 mma sm_80+)
// ---------------------------------------------------------------------------
static __device__ __forceinline__ uint32_t smem_u32(const void* p) {
    uint32_t a;
    asm("{ .reg .u64 t; cvta.to.shared.u64 t, %1; cvt.u32.u64 %0, t; }"
        : "=r"(a) : "l"(p));
    return a;
}

#define LDMX4(r, addr) \
    asm volatile("ldmatrix.sync.aligned.m8n8.x4.shared.b16 {%0,%1,%2,%3}, [%4];" \
        : "=r"((r)[0]), "=r"((r)[1]), "=r"((r)[2]), "=r"((r)[3]) : "r"(addr))

#define MMA16816(d, a, b0, b1) \
    asm volatile( \
        "mma.sync.aligned.m16n8k16.row.col.f32.bf16.bf16.f32 " \
        "{%0,%1,%2,%3}, {%4,%5,%6,%7}, {%8,%9}, {%0,%1,%2,%3};" \
        : "+f"((d)[0]), "+f"((d)[1]), "+f"((d)[2]), "+f"((d)[3]) \
        : "r"((a)[0]), "r"((a)[1]), "r"((a)[2]), "r"((a)[3]), \
          "r"(b0), "r"(b1))

#define CP_ASYNC16(dst, src) \
    asm volatile("cp.async.cg.shared.global [%0], [%1], 16;" \
        :: "r"(dst), "l"(src) : "memory")
#define CP_COMMIT() asm volatile("cp.async.commit_group;" ::: "memory")
#define CP_WAIT0()  asm volatile("cp.async.wait_group 0;" ::: "memory")

// smem row = 64B (32 bf16). Swizzle 16B chunk within row: c ^= (row>>1)&3.
static __device__ __forceinline__ uint32_t sw_off(int row, int chunk) {
    return (uint32_t)(row * 64 + ((chunk ^ ((row >> 1) & 3)) << 4));
}

// ---------------------------------------------------------------------------
// W transpose + fp32 -> bf16 hi/lo split.  Wt[n][k] = W[k][n].
// ---------------------------------------------------------------------------
__global__ __launch_bounds__(256)
void wconv_kernel(const float* __restrict__ W,
                  __nv_bfloat16* __restrict__ th, __nv_bfloat16* __restrict__ tl)
{
    __shared__ float tile[32][33];
    const int n0 = blockIdx.x * 32, k0 = blockIdx.y * 32;
    const int tx = threadIdx.x & 31, ty = threadIdx.x >> 5;
#pragma unroll
    for (int i = 0; i < 32; i += 8)
        tile[ty + i][tx] = W[(size_t)(k0 + ty + i) * FF + n0 + tx];
    __syncthreads();
#pragma unroll
    for (int i = 0; i < 32; i += 8) {
        const float x = tile[tx][ty + i];
        const __nv_bfloat16 h = __float2bfloat16(x);
        const __nv_bfloat16 l = __float2bfloat16(x - __bfloat162float(h));
        const size_t o = (size_t)(n0 + ty + i) * FF + k0 + tx;
        th[o] = h;
        tl[o] = l;
    }
}

// ---------------------------------------------------------------------------
// bf16 tensor-core GEMM with hi/lo compensation (mma.sync):
// C[M,N] = A[M,K]*W[K,N].  A fp32 (split in-kernel), W pre-split bf16 [N][K].
// CTA 128x128, 512 threads, 4x4 warp grid, warp tile 32x32, BK=32.
// Accumulates Ah*Bh + Ah*Bl + Al*Bh.  B via cp.async; one sync per chunk.
// smem/buffer (32KB): AH[0,8K) AL[8K,16K) BH[16K,24K) BL[24K,32K); 2 buffers.
// ---------------------------------------------------------------------------
#define HG_SMEM 65536

__global__ __launch_bounds__(512, 1)
void hgemm_kernel(const float* __restrict__ A,
                  const __nv_bfloat16* __restrict__ Bth,
                  const __nv_bfloat16* __restrict__ Btl,
                  float* __restrict__ C)
{
    extern __shared__ __align__(128) char smem[];
    const uint32_t sb = smem_u32(smem);

    const int tid = threadIdx.x;
    const int lane = tid & 31, wid = tid >> 5;
    const int wm = (wid & 3) * 32;        // warp m offset (4 warps down)
    const int wn = (wid >> 2) * 32;       // warp n offset (4 warps across)
    const int l15 = lane & 15, lhi = lane >> 4;
    const int bx = blockIdx.x, by = blockIdx.y;

    // A fill: 128 rows x 32 fp32 per chunk; 4 threads/row, 8 fp32 each.
    const int ar = tid >> 2, aq = tid & 3;   // row, 8-col quarter (= 16B chunk idx)
    const float* Asrc = A + (size_t)(by * 128 + ar) * FF + aq * 8;

    // B fill: 128 rows x 4 chunks of 16B per op; 1 chunk per thread.
    const int br = tid >> 2, bq = tid & 3;
    const __nv_bfloat16* Bh_src = Bth + (size_t)(bx * 128 + br) * FF + bq * 8;
    const __nv_bfloat16* Bl_src = Btl + (size_t)(bx * 128 + br) * FF + bq * 8;
    const uint32_t b_dst_off = sw_off(br, bq);

    float acc[2][4][4];
#pragma unroll
    for (int i = 0; i < 2; i++)
#pragma unroll
        for (int j = 0; j < 4; j++)
#pragma unroll
            for (int q = 0; q < 4; q++) acc[i][j][q] = 0.0f;

    float4 aR0, aR1;

    auto issue_b = [&](int ch, int buf) {
        const uint32_t d = sb + buf * 32768;
        CP_ASYNC16(d + 16384 + b_dst_off, Bh_src + ch * 32);
        CP_ASYNC16(d + 24576 + b_dst_off, Bl_src + ch * 32);
    };
    auto load_a = [&](int ch) {
        aR0 = *(const float4*)(Asrc + ch * 32);
        aR1 = *(const float4*)(Asrc + ch * 32 + 4);
    };
    auto store_a = [&](int buf) {
        __nv_bfloat162 h[4], l[4];
        h[0] = __floats2bfloat162_rn(aR0.x, aR0.y);
        h[1] = __floats2bfloat162_rn(aR0.z, aR0.w);
        h[2] = __floats2bfloat162_rn(aR1.x, aR1.y);
        h[3] = __floats2bfloat162_rn(aR1.z, aR1.w);
        l[0] = __floats2bfloat162_rn(aR0.x - __bfloat162float(h[0].x),
                                     aR0.y - __bfloat162float(h[0].y));
        l[1] = __floats2bfloat162_rn(aR0.z - __bfloat162float(h[1].x),
                                     aR0.w - __bfloat162float(h[1].y));
        l[2] = __floats2bfloat162_rn(aR1.x - __bfloat162float(h[2].x),
                                     aR1.y - __bfloat162float(h[2].y));
        l[3] = __floats2bfloat162_rn(aR1.z - __bfloat162float(h[3].x),
                                     aR1.w - __bfloat162float(h[3].y));
        uint4 uh, ul;
        memcpy(&uh.x, &h[0], 4); memcpy(&uh.y, &h[1], 4);
        memcpy(&uh.z, &h[2], 4); memcpy(&uh.w, &h[3], 4);
        memcpy(&ul.x, &l[0], 4); memcpy(&ul.y, &l[1], 4);
        memcpy(&ul.z, &l[2], 4); memcpy(&ul.w, &l[3], 4);
        const uint32_t off = sw_off(ar, aq);
        *(uint4*)(smem + buf * 32768 + off) = uh;           // AH
        *(uint4*)(smem + buf * 32768 + 8192 + off) = ul;    // AL
    };
    auto compute = [&](int buf) {
        const uint32_t bA = sb + buf * 32768;
        const uint32_t bB = bA + 16384;
#pragma unroll
        for (int kh = 0; kh < 2; kh++) {
            uint32_t fah[2][4], fal[2][4];
#pragma unroll
            for (int mt = 0; mt < 2; mt++) {
                const int r = wm + mt * 16 + l15;
                const uint32_t ad = bA + sw_off(r, 2 * kh + lhi);
                LDMX4(fah[mt], ad);
                LDMX4(fal[mt], ad + 8192);
            }
            uint32_t fbh[2][4], fbl[2][4];
#pragma unroll
            for (int np = 0; np < 2; np++) {
                const int r = wn + np * 16 + l15;
                const uint32_t bd = bB + sw_off(r, 2 * kh + lhi);
                LDMX4(fbh[np], bd);
                LDMX4(fbl[np], bd + 8192);
            }
#pragma unroll
            for (int mt = 0; mt < 2; mt++)
#pragma unroll
                for (int np = 0; np < 2; np++) {
                    MMA16816(acc[mt][2 * np],     fah[mt], fbh[np][0], fbh[np][2]);
                    MMA16816(acc[mt][2 * np + 1], fah[mt], fbh[np][1], fbh[np][3]);
                    MMA16816(acc[mt][2 * np],     fah[mt], fbl[np][0], fbl[np][2]);
                    MMA16816(acc[mt][2 * np + 1], fah[mt], fbl[np][1], fbl[np][3]);
                    MMA16816(acc[mt][2 * np],     fal[mt], fbh[np][0], fbh[np][2]);
                    MMA16816(acc[mt][2 * np + 1], fal[mt], fbh[np][1], fbh[np][3]);
                }
        }
    };

    // ---- prologue: stage chunk 0 into buffer 0 ----
    issue_b(0, 0);
    CP_COMMIT();
    load_a(0);
    store_a(0);
    CP_WAIT0();
    __syncthreads();

    const int NCH = FF / 32;  // 32
    for (int ch = 0; ch < NCH; ++ch) {
        const int cur = ch & 1;
        if (ch + 1 < NCH) {
            issue_b(ch + 1, cur ^ 1);
            CP_COMMIT();
            load_a(ch + 1);
        }
        compute(cur);
        if (ch + 1 < NCH) {
            store_a(cur ^ 1);
            CP_WAIT0();
            __syncthreads();
        }
    }

    // ---- epilogue ----
    const int g = lane >> 2, tig = lane & 3;
#pragma unroll
    for (int mt = 0; mt < 2; mt++) {
        const int row0 = by * 128 + wm + mt * 16 + g;
#pragma unroll
        for (int nt = 0; nt < 4; nt++) {
            const int col = bx * 128 + wn + nt * 8 + tig * 2;
            float* c0 = C + (size_t)row0 * FF + col;
            *(float2*)c0 = make_float2(acc[mt][nt][0], acc[mt][nt][1]);
            *(float2*)(c0 + 8 * FF) = make_float2(acc[mt][nt][2], acc[mt][nt][3]);
        }
    }
}

// ---------------------------------------------------------------------------
// Per-head LayerNorm, in place. One warp per contiguous 64-float row.
// ---------------------------------------------------------------------------
__global__ __launch_bounds__(256)
void ln_kernel(float* __restrict__ x, const float* __restrict__ scale,
               const float* __restrict__ bias)
{
    const int warp = blockIdx.x * (blockDim.x >> 5) + (threadIdx.x >> 5);
    const int lane = threadIdx.x & 31;
    if (warp >= NROWS) return;
    const int h = (warp >> 13) & (HH - 1);

    float* row = x + (size_t)warp * DD;
    float2 v = *(const float2*)(row + lane * 2);
    float s = v.x + v.y;
    float ss = v.x * v.x + v.y * v.y;
#pragma unroll
    for (int o = 16; o > 0; o >>= 1) {
        s  += __shfl_xor_sync(0xffffffffu, s,  o);
        ss += __shfl_xor_sync(0xffffffffu, ss, o);
    }
    const float mean = s * (1.0f / 64.0f);
    const float var  = ss * (1.0f / 64.0f) - mean * mean;
    const float rstd = rsqrtf(var + 1e-6f);

    const float2 sc = *(const float2*)(scale + h * DD + lane * 2);
    const float2 bi = *(const float2*)(bias  + h * DD + lane * 2);
    float2 o;
    o.x = (v.x - mean) * rstd * sc.x + bi.x;
    o.y = (v.y - mean) * rstd * sc.y + bi.y;
    *(float2*)(row + lane * 2) = o;
}

// ---------------------------------------------------------------------------
// p_attn[bh,d,e] = (1/S) * sum_n k[bh,n,d] * v[bh,n,e].
// ---------------------------------------------------------------------------
__global__ __launch_bounds__(256)
void ktv_kernel(const float* __restrict__ k, const float* __restrict__ v,
                float* __restrict__ p_out)
{
    constexpr int RB = 64;
    __shared__ __align__(16) float ks[RB][DD];
    __shared__ __align__(16) float vs[RB][DD];

    const int bh = blockIdx.y;
    const int chunk = blockIdx.x;
    const float* kb = k + ((size_t)bh * SS + chunk * 512) * DD;
    const float* vb = v + ((size_t)bh * SS + chunk * 512) * DD;

    const int tid = threadIdx.x;
    const int d0 = (tid & 15) << 2;
    const int e0 = (tid >> 4) << 2;

    float acc[4][4];
#pragma unroll
    for (int i = 0; i < 4; i++)
#pragma unroll
        for (int j = 0; j < 4; j++) acc[i][j] = 0.0f;

    for (int r0 = 0; r0 < 512; r0 += RB) {
        __syncthreads();
        for (int i = tid; i < RB * 16; i += 256) {
            const int row = i >> 4;
            const int c = (i & 15) << 2;
            *(float4*)&ks[row][c] = *(const float4*)(kb + (size_t)(r0 + row) * DD + c);
            *(float4*)&vs[row][c] = *(const float4*)(vb + (size_t)(r0 + row) * DD + c);
        }
        __syncthreads();
#pragma unroll 4
        for (int r = 0; r < RB; r++) {
            const float4 kk = *(const float4*)&ks[r][d0];
            const float4 vv = *(const float4*)&vs[r][e0];
            acc[0][0] += kk.x * vv.x; acc[0][1] += kk.x * vv.y;
            acc[0][2] += kk.x * vv.z; acc[0][3] += kk.x * vv.w;
            acc[1][0] += kk.y * vv.x; acc[1][1] += kk.y * vv.y;
            acc[1][2] += kk.y * vv.z; acc[1][3] += kk.y * vv.w;
            acc[2][0] += kk.z * vv.x; acc[2][1] += kk.z * vv.y;
            acc[2][2] += kk.z * vv.z; acc[2][3] += kk.z * vv.w;
            acc[3][0] += kk.w * vv.x; acc[3][1] += kk.w * vv.y;
            acc[3][2] += kk.w * vv.z; acc[3][3] += kk.w * vv.w;
        }
    }

    float* pb = p_out + (size_t)bh * (DD * DD);
    const float scl = 1.0f / (float)SS;
#pragma unroll
    for (int i = 0; i < 4; i++)
#pragma unroll
        for (int j = 0; j < 4; j++)
            atomicAdd(&pb[(d0 + i) * DD + (e0 + j)], acc[i][j] * scl);
}

// ---------------------------------------------------------------------------
// x[bh,n,e] = sum_d q[bh,n,d] * P[bh,d,e].
// ---------------------------------------------------------------------------
__global__ __launch_bounds__(128)
void qp_kernel(const float* __restrict__ q, const float* __restrict__ p,
               float* __restrict__ out)
{
    __shared__ __align__(16) float Ps[DD][DD];
    const int bh = blockIdx.y;
    const float* pb = p + (size_t)bh * (DD * DD);
    for (int i = threadIdx.x; i < DD * DD; i += 128)
        Ps[i >> 6][i & 63] = pb[i];
    __syncthreads();

    const int row = blockIdx.x * 128 + threadIdx.x;
    const float* qrow = q + ((size_t)bh * SS + row) * DD;

    float4 acc4[16];
#pragma unroll
    for (int j = 0; j < 16; j++) acc4[j] = make_float4(0.f, 0.f, 0.f, 0.f);

#pragma unroll 2
    for (int dq = 0; dq < DD; dq += 4) {
        const float4 qq = *(const float4*)(qrow + dq);
        const float qv[4] = {qq.x, qq.y, qq.z, qq.w};
#pragma unroll
        for (int dd = 0; dd < 4; dd++) {
            const float qs = qv[dd];
#pragma unroll
            for (int j = 0; j < 16; j++) {
                const float4 p4 = *(const float4*)&Ps[dq + dd][j * 4];
                acc4[j].x += qs * p4.x;
                acc4[j].y += qs * p4.y;
                acc4[j].z += qs * p4.z;
                acc4[j].w += qs * p4.w;
            }
        }
    }

    float* orow = out + ((size_t)bh * SS + row) * DD;
#pragma unroll
    for (int j = 0; j < 16; j++)
        *(float4*)(orow + j * 4) = acc4[j];
}

// ---------------------------------------------------------------------------
extern "C" void kernel_launch(void* const* d_in, const int* in_sizes, int n_in,
                              void* d_out, int out_size)
{
    (void)in_sizes; (void)n_in; (void)out_size;
    const float* query = (const float*)d_in[0];
    const float* key   = (const float*)d_in[1];
    const float* value = (const float*)d_in[2];
    const float* Wq    = (const float*)d_in[3];
    const float* Wk    = (const float*)d_in[4];
    const float* Wv    = (const float*)d_in[5];
    const float* lnks  = (const float*)d_in[6];
    const float* lnkb  = (const float*)d_in[7];
    const float* lnvs  = (const float*)d_in[8];
    const float* lnvb  = (const float*)d_in[9];

    float* out = (float*)d_out;
    float* att = out;
    float* p   = out + ATT_ELEMS;

    float *gq, *gk, *gv;
    cudaGetSymbolAddress((void**)&gq, g_q);
    cudaGetSymbolAddress((void**)&gk, g_k);
    cudaGetSymbolAddress((void**)&gv, g_v);
    __nv_bfloat16 *wth, *wtl;
    cudaGetSymbolAddress((void**)&wth, g_wth);
    cudaGetSymbolAddress((void**)&wtl, g_wtl);

    cudaFuncSetAttribute(hgemm_kernel,
                         cudaFuncAttributeMaxDynamicSharedMemorySize, HG_SMEM);

    // W transpose + hi/lo split
    dim3 tg(FF / 32, FF / 32);
    wconv_kernel<<<tg, 256>>>(Wq, wth, wtl);
    wconv_kernel<<<tg, 256>>>(Wk, wth + (size_t)FF * FF, wtl + (size_t)FF * FF);
    wconv_kernel<<<tg, 256>>>(Wv, wth + (size_t)2 * FF * FF, wtl + (size_t)2 * FF * FF);

    // Projections on tensor cores (mma.sync)
    dim3 gg(FF / 128, MM / 128);  // (8, 256)
    hgemm_kernel<<<gg, 512, HG_SMEM>>>(query, wth, wtl, gq);
    hgemm_kernel<<<gg, 512, HG_SMEM>>>(key, wth + (size_t)FF * FF,
                                       wtl + (size_t)FF * FF, gk);
    hgemm_kernel<<<gg, 512, HG_SMEM>>>(value, wth + (size_t)2 * FF * FF,
                                       wtl + (size_t)2 * FF * FF, gv);

    const int ln_blocks = NROWS / 8;
    ln_kernel<<<ln_blocks, 256>>>(gk, lnks, lnkb);
    ln_kernel<<<ln_blocks, 256>>>(gv, lnvs, lnvb);

    cudaMemsetAsync(p, 0, P_ELEMS * sizeof(float));
    ktv_kernel<<<dim3(16, BB * HH), 256>>>(gk, gv, p);
    qp_kernel<<<dim3(SS / 128, BB * HH), 128>>>(gq, p, att);
}

// round 7
// speedup vs baseline: 1.4882x; 1.4882x over previous
#include <cuda_runtime.h>
#include <cuda_bf16.h>
#include <cstdint>
#include <cstring>

// Problem constants
#define BB 4
#define SS 8192
#define FF 1024
#define HH 16
#define DD 64
#define MM (BB * SS)          // 32768 rows for projections
#define NROWS (BB * HH * SS)  // 524288 LN rows
#define ATT_ELEMS ((size_t)BB * SS * FF)       // 33554432
#define P_ELEMS   ((size_t)BB * HH * DD * DD)  // 262144

// Scratch (device globals: allocation-free rule)
__device__ float g_q[ATT_ELEMS];
__device__ float g_k[ATT_ELEMS];
__device__ float g_v[ATT_ELEMS];
__device__ __nv_bfloat16 g_wth[3 * FF * FF];   // W^T hi
__device__ __nv_bfloat16 g_wtl[3 * FF * FF];   // W^T lo
__device__ __nv_bfloat16 g_ah[3 * ATT_ELEMS];  // A hi (q,k,v)
__device__ __nv_bfloat16 g_al[3 * ATT_ELEMS];  // A lo (q,k,v)

// ---------------------------------------------------------------------------
// helpers
// ---------------------------------------------------------------------------
static __device__ __forceinline__ uint32_t smem_u32(const void* p) {
    uint32_t a;
    asm("{ .reg .u64 t; cvta.to.shared.u64 t, %1; cvt.u32.u64 %0, t; }"
        : "=r"(a) : "l"(p));
    return a;
}

#define LDMX4(r, addr) \
    asm volatile("ldmatrix.sync.aligned.m8n8.x4.shared.b16 {%0,%1,%2,%3}, [%4];" \
        : "=r"((r)[0]), "=r"((r)[1]), "=r"((r)[2]), "=r"((r)[3]) : "r"(addr))

#define MMA16816(d, a, b0, b1) \
    asm volatile( \
        "mma.sync.aligned.m16n8k16.row.col.f32.bf16.bf16.f32 " \
        "{%0,%1,%2,%3}, {%4,%5,%6,%7}, {%8,%9}, {%0,%1,%2,%3};" \
        : "+f"((d)[0]), "+f"((d)[1]), "+f"((d)[2]), "+f"((d)[3]) \
        : "r"((a)[0]), "r"((a)[1]), "r"((a)[2]), "r"((a)[3]), \
          "r"(b0), "r"(b1))

#define CP_ASYNC16(dst, src) \
    asm volatile("cp.async.cg.shared.global [%0], [%1], 16;" \
        :: "r"(dst), "l"(src) : "memory")
#define CP_COMMIT() asm volatile("cp.async.commit_group;" ::: "memory")
#define CP_WAIT2()  asm volatile("cp.async.wait_group 2;" ::: "memory")

// smem row = 64B (32 bf16). Swizzle 16B chunk within row: c ^= (row>>1)&3.
static __device__ __forceinline__ uint32_t sw_off(int row, int chunk) {
    return (uint32_t)(row * 64 + ((chunk ^ ((row >> 1) & 3)) << 4));
}

// fp32x8 -> bf16 hi/lo x8 (two uint4)
static __device__ __forceinline__ void split8(const float4 a, const float4 b,
                                              uint4& uh, uint4& ul)
{
    __nv_bfloat162 h[4], l[4];
    h[0] = __floats2bfloat162_rn(a.x, a.y);
    h[1] = __floats2bfloat162_rn(a.z, a.w);
    h[2] = __floats2bfloat162_rn(b.x, b.y);
    h[3] = __floats2bfloat162_rn(b.z, b.w);
    l[0] = __floats2bfloat162_rn(a.x - __bfloat162float(h[0].x),
                                 a.y - __bfloat162float(h[0].y));
    l[1] = __floats2bfloat162_rn(a.z - __bfloat162float(h[1].x),
                                 a.w - __bfloat162float(h[1].y));
    l[2] = __floats2bfloat162_rn(b.x - __bfloat162float(h[2].x),
                                 b.y - __bfloat162float(h[2].y));
    l[3] = __floats2bfloat162_rn(b.z - __bfloat162float(h[3].x),
                                 b.w - __bfloat162float(h[3].y));
    memcpy(&uh.x, &h[0], 4); memcpy(&uh.y, &h[1], 4);
    memcpy(&uh.z, &h[2], 4); memcpy(&uh.w, &h[3], 4);
    memcpy(&ul.x, &l[0], 4); memcpy(&ul.y, &l[1], 4);
    memcpy(&ul.z, &l[2], 4); memcpy(&ul.w, &l[3], 4);
}

// ---------------------------------------------------------------------------
// A fp32 -> bf16 hi/lo split (row-major [M][K], layout preserved)
// ---------------------------------------------------------------------------
__global__ __launch_bounds__(256)
void aconv_kernel(const float* __restrict__ x,
                  __nv_bfloat16* __restrict__ hi, __nv_bfloat16* __restrict__ lo)
{
    const size_t i = ((size_t)blockIdx.x * 256 + threadIdx.x) * 8;
    const float4 a = *(const float4*)(x + i);
    const float4 b = *(const float4*)(x + i + 4);
    uint4 uh, ul;
    split8(a, b, uh, ul);
    *(uint4*)(hi + i) = uh;
    *(uint4*)(lo + i) = ul;
}

// ---------------------------------------------------------------------------
// W transpose + fp32 -> bf16 hi/lo split.  Wt[n][k] = W[k][n].
// ---------------------------------------------------------------------------
__global__ __launch_bounds__(256)
void wconv_kernel(const float* __restrict__ W,
                  __nv_bfloat16* __restrict__ th, __nv_bfloat16* __restrict__ tl)
{
    __shared__ float tile[32][33];
    const int n0 = blockIdx.x * 32, k0 = blockIdx.y * 32;
    const int tx = threadIdx.x & 31, ty = threadIdx.x >> 5;
#pragma unroll
    for (int i = 0; i < 32; i += 8)
        tile[ty + i][tx] = W[(size_t)(k0 + ty + i) * FF + n0 + tx];
    __syncthreads();
#pragma unroll
    for (int i = 0; i < 32; i += 8) {
        const float x = tile[tx][ty + i];
        const __nv_bfloat16 h = __float2bfloat16(x);
        const __nv_bfloat16 l = __float2bfloat16(x - __bfloat162float(h));
        const size_t o = (size_t)(n0 + ty + i) * FF + k0 + tx;
        th[o] = h;
        tl[o] = l;
    }
}

// ---------------------------------------------------------------------------
// bf16 tensor-core GEMM, hi/lo compensated, all operands pre-split bf16.
// C[M,N] = A[M,K]*W[K,N];  A: [M][K] hi/lo,  W: [N][K] hi/lo.
// CTA 128x128, 256 threads, 8 warps (2x4), warp tile 64x32, BK=32.
// 4-stage cp.async pipeline, one __syncthreads per chunk.
// MMA order: term-outermost (hh, hl, lh) -> 16 independent MMAs between
// accumulator reuse (kills the RAW chain that capped tensor pipe at ~50%).
// stage s (32KB): AH[0,8K) AL[8K,16K) BH[16K,24K) BL[24K,32K)
// ---------------------------------------------------------------------------
#define HG_STAGES 4
#define HG_SMEM (HG_STAGES * 32768)

__global__ __launch_bounds__(256, 1)
void hgemm_kernel(const __nv_bfloat16* __restrict__ Ah,
                  const __nv_bfloat16* __restrict__ Al,
                  const __nv_bfloat16* __restrict__ Bh,
                  const __nv_bfloat16* __restrict__ Bl,
                  float* __restrict__ C)
{
    extern __shared__ __align__(128) char smem[];
    const uint32_t sb = smem_u32(smem);

    const int tid = threadIdx.x;
    const int lane = tid & 31, wid = tid >> 5;
    const int wm = (wid & 1) * 64;        // warp m offset
    const int wn = (wid >> 1) * 32;       // warp n offset
    const int l15 = lane & 15, lhi = lane >> 4;
    const int bx = blockIdx.x, by = blockIdx.y;

    // fill mapping: per array 8KB = 512 x 16B; 2 granules per thread
    const int r0 = tid >> 2, ck0 = tid & 3;          // granule 0
    const int r1 = (tid + 256) >> 2, ck1 = ck0;      // granule 1 (rows 64..127)
    const uint32_t o0 = sw_off(r0, ck0), o1 = sw_off(r1, ck1);

    const __nv_bfloat16* pAh = Ah + (size_t)(by * 128 + r0) * FF + ck0 * 8;
    const __nv_bfloat16* pAl = Al + (size_t)(by * 128 + r0) * FF + ck0 * 8;
    const __nv_bfloat16* pBh = Bh + (size_t)(bx * 128 + r0) * FF + ck0 * 8;
    const __nv_bfloat16* pBl = Bl + (size_t)(bx * 128 + r0) * FF + ck0 * 8;
    const size_t rstep = (size_t)64 * FF;  // +64 rows

    float acc[4][4][4];
#pragma unroll
    for (int i = 0; i < 4; i++)
#pragma unroll
        for (int j = 0; j < 4; j++)
#pragma unroll
            for (int q = 0; q < 4; q++) acc[i][j][q] = 0.0f;

    auto issue = [&](int ch, int stage) {
        const uint32_t d = sb + stage * 32768;
        const int kofs = ch * 32;
        CP_ASYNC16(d + o0,         pAh + kofs);
        CP_ASYNC16(d + o1,         pAh + rstep + kofs);
        CP_ASYNC16(d + 8192 + o0,  pAl + kofs);
        CP_ASYNC16(d + 8192 + o1,  pAl + rstep + kofs);
        CP_ASYNC16(d + 16384 + o0, pBh + kofs);
        CP_ASYNC16(d + 16384 + o1, pBh + rstep + kofs);
        CP_ASYNC16(d + 24576 + o0, pBl + kofs);
        CP_ASYNC16(d + 24576 + o1, pBl + rstep + kofs);
    };

    auto compute = [&](int stage) {
        const uint32_t bA = sb + stage * 32768;
        const uint32_t bB = bA + 16384;
#pragma unroll
        for (int kh = 0; kh < 2; kh++) {
            uint32_t fah[4][4], fal[4][4];
#pragma unroll
            for (int mt = 0; mt < 4; mt++) {
                const int r = wm + mt * 16 + l15;
                const uint32_t ad = bA + sw_off(r, 2 * kh + lhi);
                LDMX4(fah[mt], ad);
                LDMX4(fal[mt], ad + 8192);
            }
            uint32_t fbh[2][4], fbl[2][4];
#pragma unroll
            for (int np = 0; np < 2; np++) {
                const int r = wn + np * 16 + l15;
                const uint32_t bd = bB + sw_off(r, 2 * kh + lhi);
                LDMX4(fbh[np], bd);
                LDMX4(fbl[np], bd + 8192);
            }
            // term hh: 16 independent MMAs
#pragma unroll
            for (int mt = 0; mt < 4; mt++)
#pragma unroll
                for (int np = 0; np < 2; np++) {
                    MMA16816(acc[mt][2 * np],     fah[mt], fbh[np][0], fbh[np][2]);
                    MMA16816(acc[mt][2 * np + 1], fah[mt], fbh[np][1], fbh[np][3]);
                }
            // term hl
#pragma unroll
            for (int mt = 0; mt < 4; mt++)
#pragma unroll
                for (int np = 0; np < 2; np++) {
                    MMA16816(acc[mt][2 * np],     fah[mt], fbl[np][0], fbl[np][2]);
                    MMA16816(acc[mt][2 * np + 1], fah[mt], fbl[np][1], fbl[np][3]);
                }
            // term lh
#pragma unroll
            for (int mt = 0; mt < 4; mt++)
#pragma unroll
                for (int np = 0; np < 2; np++) {
                    MMA16816(acc[mt][2 * np],     fal[mt], fbh[np][0], fbh[np][2]);
                    MMA16816(acc[mt][2 * np + 1], fal[mt], fbh[np][1], fbh[np][3]);
                }
        }
    };

    const int NCH = FF / 32;  // 32

    // prologue: stage 0..2
#pragma unroll
    for (int s = 0; s < HG_STAGES - 1; ++s) {
        issue(s, s);
        CP_COMMIT();
    }

    for (int ch = 0; ch < NCH; ++ch) {
        CP_WAIT2();          // stage ch arrived (3 groups always in flight)
        __syncthreads();     // also protects overwrite of oldest buffer
        if (ch + HG_STAGES - 1 < NCH)
            issue(ch + HG_STAGES - 1, (ch + HG_STAGES - 1) & (HG_STAGES - 1));
        CP_COMMIT();         // empty group in tail keeps arithmetic exact
        compute(ch & (HG_STAGES - 1));
    }

    // epilogue
    const int g = lane >> 2, tig = lane & 3;
#pragma unroll
    for (int mt = 0; mt < 4; mt++) {
        const int row0 = by * 128 + wm + mt * 16 + g;
#pragma unroll
        for (int nt = 0; nt < 4; nt++) {
            const int col = bx * 128 + wn + nt * 8 + tig * 2;
            float* c0 = C + (size_t)row0 * FF + col;
            *(float2*)c0 = make_float2(acc[mt][nt][0], acc[mt][nt][1]);
            *(float2*)(c0 + 8 * FF) = make_float2(acc[mt][nt][2], acc[mt][nt][3]);
        }
    }
}

// ---------------------------------------------------------------------------
// Per-head LayerNorm on K and V, in place, fused into one launch.
// One warp per contiguous 64-float row; warps [0,NROWS) -> k, rest -> v.
// ---------------------------------------------------------------------------
__global__ __launch_bounds__(256)
void ln_kernel(float* __restrict__ k, float* __restrict__ v,
               const float* __restrict__ ks, const float* __restrict__ kb,
               const float* __restrict__ vs, const float* __restrict__ vb)
{
    const int warp = blockIdx.x * (blockDim.x >> 5) + (threadIdx.x >> 5);
    const int lane = threadIdx.x & 31;
    const int isv = warp >= NROWS;
    const int w = isv ? warp - NROWS : warp;
    const int h = (w >> 13) & (HH - 1);

    float* row = (isv ? v : k) + (size_t)w * DD;
    const float* sc_p = (isv ? vs : ks) + h * DD + lane * 2;
    const float* bi_p = (isv ? vb : kb) + h * DD + lane * 2;

    float2 x = *(const float2*)(row + lane * 2);
    float s = x.x + x.y;
    float ss = x.x * x.x + x.y * x.y;
#pragma unroll
    for (int o = 16; o > 0; o >>= 1) {
        s  += __shfl_xor_sync(0xffffffffu, s,  o);
        ss += __shfl_xor_sync(0xffffffffu, ss, o);
    }
    const float mean = s * (1.0f / 64.0f);
    const float var  = ss * (1.0f / 64.0f) - mean * mean;
    const float rstd = rsqrtf(var + 1e-6f);

    const float2 sc = *(const float2*)sc_p;
    const float2 bi = *(const float2*)bi_p;
    float2 o;
    o.x = (x.x - mean) * rstd * sc.x + bi.x;
    o.y = (x.y - mean) * rstd * sc.y + bi.y;
    *(float2*)(row + lane * 2) = o;
}

// ---------------------------------------------------------------------------
// p_attn[bh,d,e] = (1/S) * sum_n k[bh,n,d] * v[bh,n,e].
// ---------------------------------------------------------------------------
__global__ __launch_bounds__(256)
void ktv_kernel(const float* __restrict__ k, const float* __restrict__ v,
                float* __restrict__ p_out)
{
    constexpr int RB = 64;
    __shared__ __align__(16) float ks[RB][DD];
    __shared__ __align__(16) float vs[RB][DD];

    const int bh = blockIdx.y;
    const int chunk = blockIdx.x;
    const float* kb = k + ((size_t)bh * SS + chunk * 512) * DD;
    const float* vb = v + ((size_t)bh * SS + chunk * 512) * DD;

    const int tid = threadIdx.x;
    const int d0 = (tid & 15) << 2;
    const int e0 = (tid >> 4) << 2;

    float acc[4][4];
#pragma unroll
    for (int i = 0; i < 4; i++)
#pragma unroll
        for (int j = 0; j < 4; j++) acc[i][j] = 0.0f;

    for (int r0 = 0; r0 < 512; r0 += RB) {
        __syncthreads();
        for (int i = tid; i < RB * 16; i += 256) {
            const int row = i >> 4;
            const int c = (i & 15) << 2;
            *(float4*)&ks[row][c] = *(const float4*)(kb + (size_t)(r0 + row) * DD + c);
            *(float4*)&vs[row][c] = *(const float4*)(vb + (size_t)(r0 + row) * DD + c);
        }
        __syncthreads();
#pragma unroll 4
        for (int r = 0; r < RB; r++) {
            const float4 kk = *(const float4*)&ks[r][d0];
            const float4 vv = *(const float4*)&vs[r][e0];
            acc[0][0] += kk.x * vv.x; acc[0][1] += kk.x * vv.y;
            acc[0][2] += kk.x * vv.z; acc[0][3] += kk.x * vv.w;
            acc[1][0] += kk.y * vv.x; acc[1][1] += kk.y * vv.y;
            acc[1][2] += kk.y * vv.z; acc[1][3] += kk.y * vv.w;
            acc[2][0] += kk.z * vv.x; acc[2][1] += kk.z * vv.y;
            acc[2][2] += kk.z * vv.z; acc[2][3] += kk.z * vv.w;
            acc[3][0] += kk.w * vv.x; acc[3][1] += kk.w * vv.y;
            acc[3][2] += kk.w * vv.z; acc[3][3] += kk.w * vv.w;
        }
    }

    float* pb = p_out + (size_t)bh * (DD * DD);
    const float scl = 1.0f / (float)SS;
#pragma unroll
    for (int i = 0; i < 4; i++)
#pragma unroll
        for (int j = 0; j < 4; j++)
            atomicAdd(&pb[(d0 + i) * DD + (e0 + j)], acc[i][j] * scl);
}

// ---------------------------------------------------------------------------
// x[bh,n,e] = sum_d q[bh,n,d] * P[bh,d,e].
// ---------------------------------------------------------------------------
__global__ __launch_bounds__(128)
void qp_kernel(const float* __restrict__ q, const float* __restrict__ p,
               float* __restrict__ out)
{
    __shared__ __align__(16) float Ps[DD][DD];
    const int bh = blockIdx.y;
    const float* pb = p + (size_t)bh * (DD * DD);
    for (int i = threadIdx.x; i < DD * DD; i += 128)
        Ps[i >> 6][i & 63] = pb[i];
    __syncthreads();

    const int row = blockIdx.x * 128 + threadIdx.x;
    const float* qrow = q + ((size_t)bh * SS + row) * DD;

    float4 acc4[16];
#pragma unroll
    for (int j = 0; j < 16; j++) acc4[j] = make_float4(0.f, 0.f, 0.f, 0.f);

#pragma unroll 2
    for (int dq = 0; dq < DD; dq += 4) {
        const float4 qq = *(const float4*)(qrow + dq);
        const float qv[4] = {qq.x, qq.y, qq.z, qq.w};
#pragma unroll
        for (int dd = 0; dd < 4; dd++) {
            const float qs = qv[dd];
#pragma unroll
            for (int j = 0; j < 16; j++) {
                const float4 p4 = *(const float4*)&Ps[dq + dd][j * 4];
                acc4[j].x += qs * p4.x;
                acc4[j].y += qs * p4.y;
                acc4[j].z += qs * p4.z;
                acc4[j].w += qs * p4.w;
            }
        }
    }

    float* orow = out + ((size_t)bh * SS + row) * DD;
#pragma unroll
    for (int j = 0; j < 16; j++)
        *(float4*)(orow + j * 4) = acc4[j];
}

// ---------------------------------------------------------------------------
extern "C" void kernel_launch(void* const* d_in, const int* in_sizes, int n_in,
                              void* d_out, int out_size)
{
    (void)in_sizes; (void)n_in; (void)out_size;
    const float* query = (const float*)d_in[0];
    const float* key   = (const float*)d_in[1];
    const float* value = (const float*)d_in[2];
    const float* Wq    = (const float*)d_in[3];
    const float* Wk    = (const float*)d_in[4];
    const float* Wv    = (const float*)d_in[5];
    const float* lnks  = (const float*)d_in[6];
    const float* lnkb  = (const float*)d_in[7];
    const float* lnvs  = (const float*)d_in[8];
    const float* lnvb  = (const float*)d_in[9];

    float* out = (float*)d_out;
    float* att = out;
    float* p   = out + ATT_ELEMS;

    float *gq, *gk, *gv;
    cudaGetSymbolAddress((void**)&gq, g_q);
    cudaGetSymbolAddress((void**)&gk, g_k);
    cudaGetSymbolAddress((void**)&gv, g_v);
    __nv_bfloat16 *wth, *wtl, *ah, *al;
    cudaGetSymbolAddress((void**)&wth, g_wth);
    cudaGetSymbolAddress((void**)&wtl, g_wtl);
    cudaGetSymbolAddress((void**)&ah, g_ah);
    cudaGetSymbolAddress((void**)&al, g_al);

    cudaFuncSetAttribute(hgemm_kernel,
                         cudaFuncAttributeMaxDynamicSharedMemorySize, HG_SMEM);

    // Operand prep: W transpose+split, A split
    dim3 tg(FF / 32, FF / 32);
    wconv_kernel<<<tg, 256>>>(Wq, wth, wtl);
    wconv_kernel<<<tg, 256>>>(Wk, wth + (size_t)FF * FF, wtl + (size_t)FF * FF);
    wconv_kernel<<<tg, 256>>>(Wv, wth + (size_t)2 * FF * FF, wtl + (size_t)2 * FF * FF);

    const int ablocks = (int)(ATT_ELEMS / 8 / 256);  // 16384
    aconv_kernel<<<ablocks, 256>>>(query, ah, al);
    aconv_kernel<<<ablocks, 256>>>(key,   ah + ATT_ELEMS, al + ATT_ELEMS);
    aconv_kernel<<<ablocks, 256>>>(value, ah + 2 * ATT_ELEMS, al + 2 * ATT_ELEMS);

    // Projections on tensor cores
    dim3 gg(FF / 128, MM / 128);  // (8, 256)
    hgemm_kernel<<<gg, 256, HG_SMEM>>>(ah, al, wth, wtl, gq);
    hgemm_kernel<<<gg, 256, HG_SMEM>>>(ah + ATT_ELEMS, al + ATT_ELEMS,
                                       wth + (size_t)FF * FF,
                                       wtl + (size_t)FF * FF, gk);
    hgemm_kernel<<<gg, 256, HG_SMEM>>>(ah + 2 * ATT_ELEMS, al + 2 * ATT_ELEMS,
                                       wth + (size_t)2 * FF * FF,
                                       wtl + (size_t)2 * FF * FF, gv);

    // LayerNorm K and V (fused single launch)
    ln_kernel<<<2 * NROWS / 8, 256>>>(gk, gv, lnks, lnkb, lnvs, lnvb);

    cudaMemsetAsync(p, 0, P_ELEMS * sizeof(float));
    ktv_kernel<<<dim3(16, BB * HH), 256>>>(gk, gv, p);
    qp_kernel<<<dim3(SS / 128, BB * HH), 128>>>(gq, p, att);
}